// round 1
// baseline (speedup 1.0000x reference)
#include <cuda_runtime.h>
#include <math.h>
#include <stdint.h>

// Problem dims
#define BB 16
#define TT 512
#define CC 2048
#define HH 16
#define HD 128
#define ROPE_D 16
#define M1 (BB*TT)        // 8192
#define N1 (3*CC)         // 6144
#define K1 CC             // 2048

// ---------------- scratch (device globals; no allocation allowed) ----------
__device__ float g_qkv[(size_t)M1 * N1];                 // [8192,6144]
__device__ float g_q[(size_t)BB*HH*TT*HD];               // [B,H,T,hd]
__device__ float g_k[(size_t)BB*HH*TT*HD];
__device__ float g_v[(size_t)BB*HH*TT*HD];
__device__ float g_y[(size_t)M1 * CC];                   // [8192,2048] attn out

// ---------------- SGEMM: C[M,N] = A[M,K] @ B[K,N], all row-major -----------
// 128x128 block tile, BK=16, 256 threads, 8x8 microtile per thread.
#define BM 128
#define BN 128
#define BK 16
#define TM 8
#define TN 8

__global__ __launch_bounds__(256)
void sgemm_kernel(const float* __restrict__ A, const float* __restrict__ B,
                  float* __restrict__ C, int M, int N, int K)
{
    __shared__ float As[BK][BM];   // A tile stored transposed
    __shared__ float Bs[BK][BN];

    const int tid = threadIdx.x;
    const int tr  = tid / (BN / TN);   // 0..15
    const int tc  = tid % (BN / TN);   // 0..15
    const int rowBase = blockIdx.y * BM;
    const int colBase = blockIdx.x * BN;

    // global->smem load indices
    const int aRow = tid / 4;          // 0..63 (two rows: +0, +64)
    const int aCol = (tid % 4) * 4;    // 0,4,8,12
    const int bRow = tid / 32;         // 0..7  (two rows: +0, +8)
    const int bCol = (tid % 32) * 4;

    float acc[TM][TN];
#pragma unroll
    for (int i = 0; i < TM; i++)
#pragma unroll
        for (int j = 0; j < TN; j++) acc[i][j] = 0.0f;

    for (int k0 = 0; k0 < K; k0 += BK) {
#pragma unroll
        for (int i = 0; i < 2; i++) {
            int r = aRow + i * 64;
            float4 v = *(const float4*)&A[(size_t)(rowBase + r) * K + k0 + aCol];
            As[aCol + 0][r] = v.x;
            As[aCol + 1][r] = v.y;
            As[aCol + 2][r] = v.z;
            As[aCol + 3][r] = v.w;
        }
#pragma unroll
        for (int i = 0; i < 2; i++) {
            int r = bRow + i * 8;
            *(float4*)&Bs[r][bCol] =
                *(const float4*)&B[(size_t)(k0 + r) * N + colBase + bCol];
        }
        __syncthreads();

#pragma unroll
        for (int k = 0; k < BK; k++) {
            float4 a0 = *(const float4*)&As[k][tr * TM];
            float4 a1 = *(const float4*)&As[k][tr * TM + 4];
            float4 b0 = *(const float4*)&Bs[k][tc * TN];
            float4 b1 = *(const float4*)&Bs[k][tc * TN + 4];
            float ra[TM] = {a0.x, a0.y, a0.z, a0.w, a1.x, a1.y, a1.z, a1.w};
            float rb[TN] = {b0.x, b0.y, b0.z, b0.w, b1.x, b1.y, b1.z, b1.w};
#pragma unroll
            for (int i = 0; i < TM; i++)
#pragma unroll
                for (int j = 0; j < TN; j++)
                    acc[i][j] = fmaf(ra[i], rb[j], acc[i][j]);
        }
        __syncthreads();
    }

#pragma unroll
    for (int i = 0; i < TM; i++) {
        size_t off = (size_t)(rowBase + tr * TM + i) * N + colBase + tc * TN;
        *(float4*)&C[off]     = make_float4(acc[i][0], acc[i][1], acc[i][2], acc[i][3]);
        *(float4*)&C[off + 4] = make_float4(acc[i][4], acc[i][5], acc[i][6], acc[i][7]);
    }
}

// ---------------- RoPE + split/transpose ----------------------------------
// qkv: [B*T, 3*C] with col = which*C + h*HD + d
// writes q/k/v: [B,H,T,hd] ; RoPE on first 16 dims of q,k
__global__ __launch_bounds__(256)
void rope_split_kernel(const float* __restrict__ qkv,
                       float* __restrict__ q, float* __restrict__ k,
                       float* __restrict__ v)
{
    size_t idx = (size_t)blockIdx.x * blockDim.x + threadIdx.x;  // B*T*C threads
    if (idx >= (size_t)BB * TT * CC) return;
    int d = idx & (HD - 1);
    int h = (idx >> 7) & (HH - 1);
    int t = (idx >> 11) & (TT - 1);
    int b = idx >> 20;

    size_t srow = (size_t)(b * TT + t) * N1;
    size_t base = srow + h * HD + d;

    float qv = qkv[base];
    float kv = qkv[base + CC];
    float vv = qkv[base + 2 * CC];

    if (d < ROPE_D) {
        int j = (d < 8) ? d : d - 8;
        float freq = (float)t * powf(10000.0f, -(float)j / 8.0f);
        float c, s;
        sincosf(freq, &s, &c);
        if (d < 8) {
            float qo = qkv[base + 8];
            float ko = qkv[base + CC + 8];
            qv = qv * c - qo * s;
            kv = kv * c - ko * s;
        } else {
            float qo = qkv[base - 8];
            float ko = qkv[base + CC - 8];
            qv = qv * c + qo * s;
            kv = kv * c + ko * s;
        }
    }
    size_t dst = (((size_t)(b * HH + h)) * TT + t) * HD + d;
    q[dst] = qv;
    k[dst] = kv;
    v[dst] = vv;
}

// ---------------- Flash attention (fp32, causal) ---------------------------
// grid: (T/64, B*H), 256 threads. Q/K/V: [B*H, T, 128]. Y out: [B,T,C].
#define BQ 64
#define BKV 64
#define LDQ 132   // padded row stride for 128-wide tiles
#define LDP 68

__global__ __launch_bounds__(256)
void flash_attn_kernel(const float* __restrict__ Q, const float* __restrict__ K,
                       const float* __restrict__ V, float* __restrict__ Y)
{
    extern __shared__ float sm[];
    float* Qs = sm;                       // [64][132]
    float* Ks = Qs + BQ * LDQ;            // [64][132]
    float* Vs = Ks + BKV * LDQ;           // [64][132]
    float* Ps = Vs + BKV * LDQ;           // [64][68]

    const int tid = threadIdx.x;
    const int tr = tid / 16;              // 0..15 -> rows tr*4..tr*4+3
    const int tc = tid % 16;              // cols: S lanes strided, O blocked
    const int qt = blockIdx.x;
    const int bh = blockIdx.y;
    const int b = bh >> 4, h = bh & 15;
    const int q0 = qt * BQ;
    const float scale = 0.08838834764831845f;  // 1/sqrt(128)

    // load Q tile (pre-scaled)
    const size_t qbase = ((size_t)bh * TT + q0) * HD;
#pragma unroll
    for (int i = 0; i < 8; i++) {
        int f4 = tid + i * 256;           // 0..2047
        int r = f4 >> 5, c4 = (f4 & 31) * 4;
        float4 vq = *(const float4*)&Q[qbase + (size_t)r * HD + c4];
        vq.x *= scale; vq.y *= scale; vq.z *= scale; vq.w *= scale;
        *(float4*)&Qs[r * LDQ + c4] = vq;
    }

    float m[4], l[4], O[4][8];
#pragma unroll
    for (int i = 0; i < 4; i++) {
        m[i] = -1e30f; l[i] = 0.0f;
#pragma unroll
        for (int j = 0; j < 8; j++) O[i][j] = 0.0f;
    }

    for (int jt = 0; jt <= qt; jt++) {
        __syncthreads();   // protect K/V/P smem reuse (also orders Qs on iter 0)
        const size_t kbase = ((size_t)bh * TT + jt * BKV) * HD;
#pragma unroll
        for (int i = 0; i < 8; i++) {
            int f4 = tid + i * 256;
            int r = f4 >> 5, c4 = (f4 & 31) * 4;
            *(float4*)&Ks[r * LDQ + c4] = *(const float4*)&K[kbase + (size_t)r * HD + c4];
            *(float4*)&Vs[r * LDQ + c4] = *(const float4*)&V[kbase + (size_t)r * HD + c4];
        }
        __syncthreads();

        // S = Q K^T (4 rows x 4 strided cols per thread)
        float s[4][4];
#pragma unroll
        for (int i = 0; i < 4; i++)
#pragma unroll
            for (int j = 0; j < 4; j++) s[i][j] = 0.0f;

#pragma unroll 8
        for (int kk = 0; kk < HD; kk++) {
            float ra[4], rb[4];
#pragma unroll
            for (int i = 0; i < 4; i++) ra[i] = Qs[(tr * 4 + i) * LDQ + kk];
#pragma unroll
            for (int j = 0; j < 4; j++) rb[j] = Ks[(tc + j * 16) * LDQ + kk];
#pragma unroll
            for (int i = 0; i < 4; i++)
#pragma unroll
                for (int j = 0; j < 4; j++)
                    s[i][j] = fmaf(ra[i], rb[j], s[i][j]);
        }

        if (jt == qt) {  // causal mask on diagonal tile
#pragma unroll
            for (int i = 0; i < 4; i++) {
                int qi = q0 + tr * 4 + i;
#pragma unroll
                for (int j = 0; j < 4; j++) {
                    int ki = jt * BKV + tc + j * 16;
                    if (ki > qi) s[i][j] = -1e30f;
                }
            }
        }

        // online softmax per row (16 lanes own one row group)
#pragma unroll
        for (int i = 0; i < 4; i++) {
            float mx = fmaxf(fmaxf(s[i][0], s[i][1]), fmaxf(s[i][2], s[i][3]));
#pragma unroll
            for (int off = 8; off >= 1; off >>= 1)
                mx = fmaxf(mx, __shfl_xor_sync(0xffffffffu, mx, off));
            float newm = fmaxf(m[i], mx);
            float alpha = __expf(m[i] - newm);
            float p[4], sum = 0.0f;
#pragma unroll
            for (int j = 0; j < 4; j++) { p[j] = __expf(s[i][j] - newm); sum += p[j]; }
#pragma unroll
            for (int off = 8; off >= 1; off >>= 1)
                sum += __shfl_xor_sync(0xffffffffu, sum, off);
            l[i] = l[i] * alpha + sum;
            m[i] = newm;
#pragma unroll
            for (int j = 0; j < 8; j++) O[i][j] *= alpha;
#pragma unroll
            for (int j = 0; j < 4; j++)
                Ps[(tr * 4 + i) * LDP + tc + j * 16] = p[j];
        }
        __syncthreads();

        // O += P @ V  (O cols blocked: tc*8..tc*8+7)
#pragma unroll 4
        for (int kk = 0; kk < BKV; kk++) {
            float pa[4];
#pragma unroll
            for (int i = 0; i < 4; i++) pa[i] = Ps[(tr * 4 + i) * LDP + kk];
            float4 v0 = *(const float4*)&Vs[kk * LDQ + tc * 8];
            float4 v1 = *(const float4*)&Vs[kk * LDQ + tc * 8 + 4];
#pragma unroll
            for (int i = 0; i < 4; i++) {
                O[i][0] = fmaf(pa[i], v0.x, O[i][0]);
                O[i][1] = fmaf(pa[i], v0.y, O[i][1]);
                O[i][2] = fmaf(pa[i], v0.z, O[i][2]);
                O[i][3] = fmaf(pa[i], v0.w, O[i][3]);
                O[i][4] = fmaf(pa[i], v1.x, O[i][4]);
                O[i][5] = fmaf(pa[i], v1.y, O[i][5]);
                O[i][6] = fmaf(pa[i], v1.z, O[i][6]);
                O[i][7] = fmaf(pa[i], v1.w, O[i][7]);
            }
        }
    }

    // epilogue: normalize + write Y[B,T,C]
#pragma unroll
    for (int i = 0; i < 4; i++) {
        float inv = 1.0f / l[i];
        size_t row = (size_t)(b * TT + q0 + tr * 4 + i);
        size_t off = row * CC + h * HD + tc * 8;
        *(float4*)&Y[off]     = make_float4(O[i][0]*inv, O[i][1]*inv, O[i][2]*inv, O[i][3]*inv);
        *(float4*)&Y[off + 4] = make_float4(O[i][4]*inv, O[i][5]*inv, O[i][6]*inv, O[i][7]*inv);
    }
}

// ---------------- launch ----------------------------------------------------
extern "C" void kernel_launch(void* const* d_in, const int* in_sizes, int n_in,
                              void* d_out, int out_size)
{
    const float* x    = (const float*)d_in[0];
    const float* Wqkv = (const float*)d_in[1];
    const float* Wout = (const float*)d_in[2];
    float* out = (float*)d_out;

    float *qkv, *q, *k, *v, *y;
    cudaGetSymbolAddress((void**)&qkv, g_qkv);
    cudaGetSymbolAddress((void**)&q,   g_q);
    cudaGetSymbolAddress((void**)&k,   g_k);
    cudaGetSymbolAddress((void**)&v,   g_v);
    cudaGetSymbolAddress((void**)&y,   g_y);

    const size_t flash_smem = (size_t)(BQ * LDQ * 3 + BQ * LDP) * sizeof(float);
    cudaFuncSetAttribute(flash_attn_kernel,
                         cudaFuncAttributeMaxDynamicSharedMemorySize,
                         (int)flash_smem);

    // 1. QKV projection: [8192,2048] @ [2048,6144]
    sgemm_kernel<<<dim3(N1 / BN, M1 / BM), 256>>>(x, Wqkv, qkv, M1, N1, K1);

    // 2. RoPE + split to [B,H,T,hd]
    {
        size_t total = (size_t)BB * TT * CC;
        rope_split_kernel<<<(unsigned)((total + 255) / 256), 256>>>(qkv, q, k, v);
    }

    // 3. Flash attention (causal)
    flash_attn_kernel<<<dim3(TT / BQ, BB * HH), 256, flash_smem>>>(q, k, v, y);

    // 4. Output projection: [8192,2048] @ [2048,2048]
    sgemm_kernel<<<dim3(CC / BN, M1 / BM), 256>>>(y, Wout, out, M1, CC, K1);
}

// round 3
// speedup vs baseline: 1.8392x; 1.8392x over previous
#include <cuda_runtime.h>
#include <cuda_bf16.h>
#include <math.h>
#include <stdint.h>

// Problem dims
#define BB 16
#define TT 512
#define CC 2048
#define HH 16
#define HD 128
#define ROPE_D 16
#define M1 (BB*TT)        // 8192
#define N1 (3*CC)         // 6144
#define K1 CC             // 2048

// ---------------- scratch (device globals; no allocation allowed) ----------
__device__ float g_qkv[(size_t)M1 * N1];                 // [8192,6144]
__device__ float g_q[(size_t)BB*HH*TT*HD];               // [B,H,T,hd]
__device__ float g_k[(size_t)BB*HH*TT*HD];
__device__ float g_v[(size_t)BB*HH*TT*HD];
__device__ float g_y[(size_t)M1 * CC];                   // [8192,2048] attn out

// bf16 hi/lo scratch
__device__ __nv_bfloat16 g_xh[(size_t)M1 * K1];
__device__ __nv_bfloat16 g_xl[(size_t)M1 * K1];
__device__ __nv_bfloat16 g_wqh[(size_t)N1 * K1];         // Wqkv^T [6144,2048]
__device__ __nv_bfloat16 g_wql[(size_t)N1 * K1];
__device__ __nv_bfloat16 g_woh[(size_t)CC * CC];         // Wout^T [2048,2048]
__device__ __nv_bfloat16 g_wol[(size_t)CC * CC];
__device__ __nv_bfloat16 g_yh[(size_t)M1 * CC];
__device__ __nv_bfloat16 g_yl[(size_t)M1 * CC];

// ======================= PTX helpers (baseline ISA only) ===================
__device__ __forceinline__ uint32_t smem_u32(const void* p) {
    uint32_t a;
    asm("{ .reg .u64 t; cvta.to.shared.u64 t, %1; cvt.u32.u64 %0, t; }"
        : "=r"(a) : "l"(p));
    return a;
}
__device__ __forceinline__ void cpasync16(uint32_t dst, const void* src) {
    asm volatile("cp.async.cg.shared.global [%0], [%1], 16;"
                 :: "r"(dst), "l"(src) : "memory");
}
__device__ __forceinline__ void cpasync_commit() {
    asm volatile("cp.async.commit_group;" ::: "memory");
}
__device__ __forceinline__ void cpasync_wait1() {
    asm volatile("cp.async.wait_group 1;" ::: "memory");
}
__device__ __forceinline__ void ldsm_x4(uint32_t& r0, uint32_t& r1,
                                        uint32_t& r2, uint32_t& r3, uint32_t a) {
    asm volatile("ldmatrix.sync.aligned.m8n8.x4.shared.b16 {%0,%1,%2,%3}, [%4];"
                 : "=r"(r0), "=r"(r1), "=r"(r2), "=r"(r3) : "r"(a));
}
__device__ __forceinline__ void mma16816(float* d, const uint32_t* a,
                                         const uint32_t* b) {
    asm volatile(
        "mma.sync.aligned.m16n8k16.row.col.f32.bf16.bf16.f32 "
        "{%0,%1,%2,%3}, {%4,%5,%6,%7}, {%8,%9}, {%0,%1,%2,%3};"
        : "+f"(d[0]), "+f"(d[1]), "+f"(d[2]), "+f"(d[3])
        : "r"(a[0]), "r"(a[1]), "r"(a[2]), "r"(a[3]), "r"(b[0]), "r"(b[1]));
}

// ======================= mma.sync split-bf16 GEMM ==========================
// C[M,N] (f32) = Ah/Al [M,K] bf16 @ (Bh/Bl [N,K] bf16)^T via 3 MMA products.
#define GBM 128
#define GBN 128
#define GBK 32
#define ROWB 80                      // padded smem row stride (64B data)
#define TILE_B (128 * ROWB)          // 10240 B per tile
#define STG_B  (4 * TILE_B)          // Ah, Al, Bh, Bl
#define NSTAGE 3

__device__ __forceinline__ void g2s_stage(
    uint32_t sbase,
    const __nv_bfloat16* __restrict__ Ah, const __nv_bfloat16* __restrict__ Al,
    const __nv_bfloat16* __restrict__ Bh, const __nv_bfloat16* __restrict__ Bl,
    int m0, int n0, int k0, int K, int tid)
{
#pragma unroll
    for (int i = 0; i < 2; i++) {
        int s = tid + i * 256;               // 0..511
        int r = s >> 2, c = s & 3;           // row 0..127, 16B chunk 0..3
        uint32_t so = (uint32_t)(r * ROWB + c * 16);
        size_t ga = (size_t)(m0 + r) * K + k0 + c * 8;
        size_t gb = (size_t)(n0 + r) * K + k0 + c * 8;
        cpasync16(sbase + 0 * TILE_B + so, Ah + ga);
        cpasync16(sbase + 1 * TILE_B + so, Al + ga);
        cpasync16(sbase + 2 * TILE_B + so, Bh + gb);
        cpasync16(sbase + 3 * TILE_B + so, Bl + gb);
    }
}

__global__ __launch_bounds__(256, 1)
void gemm_mma_kernel(const __nv_bfloat16* __restrict__ Ah,
                     const __nv_bfloat16* __restrict__ Al,
                     const __nv_bfloat16* __restrict__ Bh,
                     const __nv_bfloat16* __restrict__ Bl,
                     float* __restrict__ C, int M, int N, int K)
{
    extern __shared__ char sm_raw[];
    const uint32_t smbase = smem_u32(sm_raw);
    const int tid = threadIdx.x, wid = tid >> 5, lane = tid & 31;
    const int wm = (wid >> 2) * 64;          // warp M offset: 0 / 64
    const int wn = (wid & 3) * 32;           // warp N offset: 0/32/64/96
    const int m0 = blockIdx.y * GBM;
    const int n0 = blockIdx.x * GBN;
    const int lrow = lane & 15;
    const int lch  = (lane >> 4) & 1;        // +1 chunk for k8..15 matrices

    float acc[4][4][4];
#pragma unroll
    for (int a = 0; a < 4; a++)
#pragma unroll
        for (int b = 0; b < 4; b++)
#pragma unroll
            for (int c = 0; c < 4; c++) acc[a][b][c] = 0.0f;

    g2s_stage(smbase + 0 * STG_B, Ah, Al, Bh, Bl, m0, n0, 0, K, tid);
    cpasync_commit();
    g2s_stage(smbase + 1 * STG_B, Ah, Al, Bh, Bl, m0, n0, GBK, K, tid);
    cpasync_commit();

    const int niter = K / GBK;               // 64
    int stage = 0, nstage = 2;
    for (int it = 0; it < niter; ++it) {
        cpasync_wait1();
        __syncthreads();

        if (it + 2 < niter)
            g2s_stage(smbase + nstage * STG_B, Ah, Al, Bh, Bl,
                      m0, n0, (it + 2) * GBK, K, tid);
        cpasync_commit();
        if (++nstage == NSTAGE) nstage = 0;

        const uint32_t sb = smbase + stage * STG_B;
        if (++stage == NSTAGE) stage = 0;

#pragma unroll
        for (int kb = 0; kb < 2; ++kb) {
            const int chunk = kb * 2 + lch;
            uint32_t ah[4][4], al[4][4];
#pragma unroll
            for (int mf = 0; mf < 4; ++mf) {
                uint32_t off = (uint32_t)((wm + mf * 16 + lrow) * ROWB + chunk * 16);
                ldsm_x4(ah[mf][0], ah[mf][1], ah[mf][2], ah[mf][3],
                        sb + 0 * TILE_B + off);
                ldsm_x4(al[mf][0], al[mf][1], al[mf][2], al[mf][3],
                        sb + 1 * TILE_B + off);
            }
            uint32_t bh[4][2], bl[4][2];
#pragma unroll
            for (int np = 0; np < 2; ++np) {
                uint32_t off = (uint32_t)((wn + np * 16 + lrow) * ROWB + chunk * 16);
                uint32_t r0, r1, r2, r3;
                ldsm_x4(r0, r1, r2, r3, sb + 2 * TILE_B + off);
                bh[np*2][0] = r0; bh[np*2][1] = r2;
                bh[np*2+1][0] = r1; bh[np*2+1][1] = r3;
                ldsm_x4(r0, r1, r2, r3, sb + 3 * TILE_B + off);
                bl[np*2][0] = r0; bl[np*2][1] = r2;
                bl[np*2+1][0] = r1; bl[np*2+1][1] = r3;
            }
#pragma unroll
            for (int mf = 0; mf < 4; ++mf)
#pragma unroll
                for (int nf = 0; nf < 4; ++nf) {
                    mma16816(acc[mf][nf], ah[mf], bh[nf]);
                    mma16816(acc[mf][nf], ah[mf], bl[nf]);
                    mma16816(acc[mf][nf], al[mf], bh[nf]);
                }
        }
    }

    // epilogue
    const int l4 = lane >> 2, l2 = (lane & 3) * 2;
#pragma unroll
    for (int mf = 0; mf < 4; ++mf) {
        int r0 = m0 + wm + mf * 16 + l4;
#pragma unroll
        for (int nf = 0; nf < 4; ++nf) {
            int cx = n0 + wn + nf * 8 + l2;
            *(float2*)&C[(size_t)r0 * N + cx] =
                make_float2(acc[mf][nf][0], acc[mf][nf][1]);
            *(float2*)&C[(size_t)(r0 + 8) * N + cx] =
                make_float2(acc[mf][nf][2], acc[mf][nf][3]);
        }
    }
}

// ======================= conversion kernels ================================
__global__ __launch_bounds__(256)
void split_kernel(const float* __restrict__ in, __nv_bfloat16* __restrict__ hi,
                  __nv_bfloat16* __restrict__ lo, size_t n)
{
    size_t i = ((size_t)blockIdx.x * blockDim.x + threadIdx.x) * 4;
    if (i >= n) return;
    float4 x = *(const float4*)(in + i);
    __nv_bfloat16 h0 = __float2bfloat16(x.x), h1 = __float2bfloat16(x.y);
    __nv_bfloat16 h2 = __float2bfloat16(x.z), h3 = __float2bfloat16(x.w);
    __nv_bfloat162* hp = (__nv_bfloat162*)(hi + i);
    __nv_bfloat162* lp = (__nv_bfloat162*)(lo + i);
    hp[0] = __nv_bfloat162(h0, h1);
    hp[1] = __nv_bfloat162(h2, h3);
    lp[0] = __nv_bfloat162(__float2bfloat16(x.x - __bfloat162float(h0)),
                           __float2bfloat16(x.y - __bfloat162float(h1)));
    lp[1] = __nv_bfloat162(__float2bfloat16(x.z - __bfloat162float(h2)),
                           __float2bfloat16(x.w - __bfloat162float(h3)));
}

// W [K,N] f32 -> Th/Tl [N,K] bf16
__global__ __launch_bounds__(256)
void transpose_split_kernel(const float* __restrict__ W,
                            __nv_bfloat16* __restrict__ Th,
                            __nv_bfloat16* __restrict__ Tl, int K, int N)
{
    __shared__ float tile[32][33];
    int n0 = blockIdx.x * 32, k0 = blockIdx.y * 32;
    int tx = threadIdx.x, ty = threadIdx.y;   // 32 x 8
#pragma unroll
    for (int i = 0; i < 32; i += 8)
        tile[ty + i][tx] = W[(size_t)(k0 + ty + i) * N + n0 + tx];
    __syncthreads();
#pragma unroll
    for (int i = 0; i < 32; i += 8) {
        float x = tile[tx][ty + i];
        __nv_bfloat16 h = __float2bfloat16(x);
        size_t o = (size_t)(n0 + ty + i) * K + k0 + tx;
        Th[o] = h;
        Tl[o] = __float2bfloat16(x - __bfloat162float(h));
    }
}

// ---------------- RoPE + split/transpose ----------------------------------
__global__ __launch_bounds__(256)
void rope_split_kernel(const float* __restrict__ qkv,
                       float* __restrict__ q, float* __restrict__ k,
                       float* __restrict__ v)
{
    size_t idx = (size_t)blockIdx.x * blockDim.x + threadIdx.x;
    if (idx >= (size_t)BB * TT * CC) return;
    int d = idx & (HD - 1);
    int h = (idx >> 7) & (HH - 1);
    int t = (idx >> 11) & (TT - 1);
    int b = idx >> 20;

    size_t srow = (size_t)(b * TT + t) * N1;
    size_t base = srow + h * HD + d;

    float qv = qkv[base];
    float kv = qkv[base + CC];
    float vv = qkv[base + 2 * CC];

    if (d < ROPE_D) {
        int j = (d < 8) ? d : d - 8;
        float freq = (float)t * powf(10000.0f, -(float)j / 8.0f);
        float c, s;
        sincosf(freq, &s, &c);
        if (d < 8) {
            float qo = qkv[base + 8];
            float ko = qkv[base + CC + 8];
            qv = qv * c - qo * s;
            kv = kv * c - ko * s;
        } else {
            float qo = qkv[base - 8];
            float ko = qkv[base + CC - 8];
            qv = qv * c + qo * s;
            kv = kv * c + ko * s;
        }
    }
    size_t dst = (((size_t)(b * HH + h)) * TT + t) * HD + d;
    q[dst] = qv;
    k[dst] = kv;
    v[dst] = vv;
}

// ---------------- Flash attention (fp32, causal) ---------------------------
#define BQ 64
#define BKV 64
#define LDQ 132
#define LDP 68

__global__ __launch_bounds__(256)
void flash_attn_kernel(const float* __restrict__ Q, const float* __restrict__ K,
                       const float* __restrict__ V, float* __restrict__ Y)
{
    extern __shared__ float sm[];
    float* Qs = sm;
    float* Ks = Qs + BQ * LDQ;
    float* Vs = Ks + BKV * LDQ;
    float* Ps = Vs + BKV * LDQ;

    const int tid = threadIdx.x;
    const int tr = tid / 16;
    const int tc = tid % 16;
    const int qt = blockIdx.x;
    const int bh = blockIdx.y;
    const int b = bh >> 4, h = bh & 15;
    const int q0 = qt * BQ;
    const float scale = 0.08838834764831845f;

    const size_t qbase = ((size_t)bh * TT + q0) * HD;
#pragma unroll
    for (int i = 0; i < 8; i++) {
        int f4 = tid + i * 256;
        int r = f4 >> 5, c4 = (f4 & 31) * 4;
        float4 vq = *(const float4*)&Q[qbase + (size_t)r * HD + c4];
        vq.x *= scale; vq.y *= scale; vq.z *= scale; vq.w *= scale;
        *(float4*)&Qs[r * LDQ + c4] = vq;
    }

    float m[4], l[4], O[4][8];
#pragma unroll
    for (int i = 0; i < 4; i++) {
        m[i] = -1e30f; l[i] = 0.0f;
#pragma unroll
        for (int j = 0; j < 8; j++) O[i][j] = 0.0f;
    }

    for (int jt = 0; jt <= qt; jt++) {
        __syncthreads();
        const size_t kbase = ((size_t)bh * TT + jt * BKV) * HD;
#pragma unroll
        for (int i = 0; i < 8; i++) {
            int f4 = tid + i * 256;
            int r = f4 >> 5, c4 = (f4 & 31) * 4;
            *(float4*)&Ks[r * LDQ + c4] = *(const float4*)&K[kbase + (size_t)r * HD + c4];
            *(float4*)&Vs[r * LDQ + c4] = *(const float4*)&V[kbase + (size_t)r * HD + c4];
        }
        __syncthreads();

        float s[4][4];
#pragma unroll
        for (int i = 0; i < 4; i++)
#pragma unroll
            for (int j = 0; j < 4; j++) s[i][j] = 0.0f;

#pragma unroll 8
        for (int kk = 0; kk < HD; kk++) {
            float ra[4], rb[4];
#pragma unroll
            for (int i = 0; i < 4; i++) ra[i] = Qs[(tr * 4 + i) * LDQ + kk];
#pragma unroll
            for (int j = 0; j < 4; j++) rb[j] = Ks[(tc + j * 16) * LDQ + kk];
#pragma unroll
            for (int i = 0; i < 4; i++)
#pragma unroll
                for (int j = 0; j < 4; j++)
                    s[i][j] = fmaf(ra[i], rb[j], s[i][j]);
        }

        if (jt == qt) {
#pragma unroll
            for (int i = 0; i < 4; i++) {
                int qi = q0 + tr * 4 + i;
#pragma unroll
                for (int j = 0; j < 4; j++) {
                    int ki = jt * BKV + tc + j * 16;
                    if (ki > qi) s[i][j] = -1e30f;
                }
            }
        }

#pragma unroll
        for (int i = 0; i < 4; i++) {
            float mx = fmaxf(fmaxf(s[i][0], s[i][1]), fmaxf(s[i][2], s[i][3]));
#pragma unroll
            for (int off = 8; off >= 1; off >>= 1)
                mx = fmaxf(mx, __shfl_xor_sync(0xffffffffu, mx, off));
            float newm = fmaxf(m[i], mx);
            float alpha = __expf(m[i] - newm);
            float p[4], sum = 0.0f;
#pragma unroll
            for (int j = 0; j < 4; j++) { p[j] = __expf(s[i][j] - newm); sum += p[j]; }
#pragma unroll
            for (int off = 8; off >= 1; off >>= 1)
                sum += __shfl_xor_sync(0xffffffffu, sum, off);
            l[i] = l[i] * alpha + sum;
            m[i] = newm;
#pragma unroll
            for (int j = 0; j < 8; j++) O[i][j] *= alpha;
#pragma unroll
            for (int j = 0; j < 4; j++)
                Ps[(tr * 4 + i) * LDP + tc + j * 16] = p[j];
        }
        __syncthreads();

#pragma unroll 4
        for (int kk = 0; kk < BKV; kk++) {
            float pa[4];
#pragma unroll
            for (int i = 0; i < 4; i++) pa[i] = Ps[(tr * 4 + i) * LDP + kk];
            float4 v0 = *(const float4*)&Vs[kk * LDQ + tc * 8];
            float4 v1 = *(const float4*)&Vs[kk * LDQ + tc * 8 + 4];
#pragma unroll
            for (int i = 0; i < 4; i++) {
                O[i][0] = fmaf(pa[i], v0.x, O[i][0]);
                O[i][1] = fmaf(pa[i], v0.y, O[i][1]);
                O[i][2] = fmaf(pa[i], v0.z, O[i][2]);
                O[i][3] = fmaf(pa[i], v0.w, O[i][3]);
                O[i][4] = fmaf(pa[i], v1.x, O[i][4]);
                O[i][5] = fmaf(pa[i], v1.y, O[i][5]);
                O[i][6] = fmaf(pa[i], v1.z, O[i][6]);
                O[i][7] = fmaf(pa[i], v1.w, O[i][7]);
            }
        }
    }

#pragma unroll
    for (int i = 0; i < 4; i++) {
        float inv = 1.0f / l[i];
        size_t row = (size_t)(b * TT + q0 + tr * 4 + i);
        size_t off = row * CC + h * HD + tc * 8;
        *(float4*)&Y[off]     = make_float4(O[i][0]*inv, O[i][1]*inv, O[i][2]*inv, O[i][3]*inv);
        *(float4*)&Y[off + 4] = make_float4(O[i][4]*inv, O[i][5]*inv, O[i][6]*inv, O[i][7]*inv);
    }
}

// ---------------- launch ----------------------------------------------------
extern "C" void kernel_launch(void* const* d_in, const int* in_sizes, int n_in,
                              void* d_out, int out_size)
{
    const float* x    = (const float*)d_in[0];
    const float* Wqkv = (const float*)d_in[1];
    const float* Wout = (const float*)d_in[2];
    float* out = (float*)d_out;

    float *qkv, *q, *k, *v, *y;
    cudaGetSymbolAddress((void**)&qkv, g_qkv);
    cudaGetSymbolAddress((void**)&q,   g_q);
    cudaGetSymbolAddress((void**)&k,   g_k);
    cudaGetSymbolAddress((void**)&v,   g_v);
    cudaGetSymbolAddress((void**)&y,   g_y);
    __nv_bfloat16 *xh, *xl, *wqh, *wql, *woh, *wol, *yh, *yl;
    cudaGetSymbolAddress((void**)&xh,  g_xh);
    cudaGetSymbolAddress((void**)&xl,  g_xl);
    cudaGetSymbolAddress((void**)&wqh, g_wqh);
    cudaGetSymbolAddress((void**)&wql, g_wql);
    cudaGetSymbolAddress((void**)&woh, g_woh);
    cudaGetSymbolAddress((void**)&wol, g_wol);
    cudaGetSymbolAddress((void**)&yh,  g_yh);
    cudaGetSymbolAddress((void**)&yl,  g_yl);

    const size_t flash_smem = (size_t)(BQ * LDQ * 3 + BQ * LDP) * sizeof(float);
    cudaFuncSetAttribute(flash_attn_kernel,
                         cudaFuncAttributeMaxDynamicSharedMemorySize,
                         (int)flash_smem);
    cudaFuncSetAttribute(gemm_mma_kernel,
                         cudaFuncAttributeMaxDynamicSharedMemorySize,
                         NSTAGE * STG_B);

    // 0a. split x -> bf16 hi/lo
    {
        size_t n = (size_t)M1 * K1;
        split_kernel<<<(unsigned)(n / 4 / 256), 256>>>(x, xh, xl, n);
    }
    // 0b. transpose+split weights
    transpose_split_kernel<<<dim3(N1 / 32, K1 / 32), dim3(32, 8)>>>(Wqkv, wqh, wql, K1, N1);
    transpose_split_kernel<<<dim3(CC / 32, K1 / 32), dim3(32, 8)>>>(Wout, woh, wol, K1, CC);

    // 1. QKV projection (mma.sync bf16x3): [8192,2048] @ [2048,6144]
    gemm_mma_kernel<<<dim3(N1 / GBN, M1 / GBM), 256, NSTAGE * STG_B>>>(
        xh, xl, wqh, wql, qkv, M1, N1, K1);

    // 2. RoPE + split to [B,H,T,hd]
    {
        size_t total = (size_t)BB * TT * CC;
        rope_split_kernel<<<(unsigned)((total + 255) / 256), 256>>>(qkv, q, k, v);
    }

    // 3. Flash attention (causal)
    flash_attn_kernel<<<dim3(TT / BQ, BB * HH), 256, flash_smem>>>(q, k, v, y);

    // 4. split y, then output projection
    {
        size_t n = (size_t)M1 * CC;
        split_kernel<<<(unsigned)(n / 4 / 256), 256>>>(y, yh, yl, n);
    }
    gemm_mma_kernel<<<dim3(CC / GBN, M1 / GBM), 256, NSTAGE * STG_B>>>(
        yh, yl, woh, wol, out, M1, CC, K1);
}

// round 4
// speedup vs baseline: 2.2802x; 1.2398x over previous
#include <cuda_runtime.h>
#include <cuda_bf16.h>
#include <math.h>
#include <stdint.h>

// Problem dims
#define BB 16
#define TT 512
#define CC 2048
#define HH 16
#define HD 128
#define ROPE_D 16
#define M1 (BB*TT)        // 8192
#define N1 (3*CC)         // 6144
#define K1 CC             // 2048

// ---------------- scratch (device globals; no allocation allowed) ----------
__device__ float g_qkv[(size_t)M1 * N1];                 // [8192,6144]

// bf16 hi/lo scratch
__device__ __nv_bfloat16 g_xh[(size_t)M1 * K1];
__device__ __nv_bfloat16 g_xl[(size_t)M1 * K1];
__device__ __nv_bfloat16 g_wqh[(size_t)N1 * K1];         // Wqkv^T [6144,2048]
__device__ __nv_bfloat16 g_wql[(size_t)N1 * K1];
__device__ __nv_bfloat16 g_woh[(size_t)CC * CC];         // Wout^T [2048,2048]
__device__ __nv_bfloat16 g_wol[(size_t)CC * CC];
__device__ __nv_bfloat16 g_yh[(size_t)M1 * CC];
__device__ __nv_bfloat16 g_yl[(size_t)M1 * CC];
// q/k/v hi/lo, [B*H, T, 128]
__device__ __nv_bfloat16 g_q_h[(size_t)BB*HH*TT*HD];
__device__ __nv_bfloat16 g_q_l[(size_t)BB*HH*TT*HD];
__device__ __nv_bfloat16 g_k_h[(size_t)BB*HH*TT*HD];
__device__ __nv_bfloat16 g_k_l[(size_t)BB*HH*TT*HD];
__device__ __nv_bfloat16 g_v_h[(size_t)BB*HH*TT*HD];
__device__ __nv_bfloat16 g_v_l[(size_t)BB*HH*TT*HD];

// ======================= PTX helpers (baseline ISA only) ===================
__device__ __forceinline__ uint32_t smem_u32(const void* p) {
    uint32_t a;
    asm("{ .reg .u64 t; cvta.to.shared.u64 t, %1; cvt.u32.u64 %0, t; }"
        : "=r"(a) : "l"(p));
    return a;
}
__device__ __forceinline__ void cpasync16(uint32_t dst, const void* src) {
    asm volatile("cp.async.cg.shared.global [%0], [%1], 16;"
                 :: "r"(dst), "l"(src) : "memory");
}
__device__ __forceinline__ void cpasync_commit() {
    asm volatile("cp.async.commit_group;" ::: "memory");
}
__device__ __forceinline__ void cpasync_wait1() {
    asm volatile("cp.async.wait_group 1;" ::: "memory");
}
__device__ __forceinline__ void cpasync_wait0() {
    asm volatile("cp.async.wait_group 0;" ::: "memory");
}
__device__ __forceinline__ void ldsm_x4(uint32_t& r0, uint32_t& r1,
                                        uint32_t& r2, uint32_t& r3, uint32_t a) {
    asm volatile("ldmatrix.sync.aligned.m8n8.x4.shared.b16 {%0,%1,%2,%3}, [%4];"
                 : "=r"(r0), "=r"(r1), "=r"(r2), "=r"(r3) : "r"(a));
}
__device__ __forceinline__ void ldsm_x4_t(uint32_t& r0, uint32_t& r1,
                                          uint32_t& r2, uint32_t& r3, uint32_t a) {
    asm volatile("ldmatrix.sync.aligned.m8n8.x4.trans.shared.b16 {%0,%1,%2,%3}, [%4];"
                 : "=r"(r0), "=r"(r1), "=r"(r2), "=r"(r3) : "r"(a));
}
__device__ __forceinline__ void mma16816(float* d, const uint32_t* a,
                                         const uint32_t* b) {
    asm volatile(
        "mma.sync.aligned.m16n8k16.row.col.f32.bf16.bf16.f32 "
        "{%0,%1,%2,%3}, {%4,%5,%6,%7}, {%8,%9}, {%0,%1,%2,%3};"
        : "+f"(d[0]), "+f"(d[1]), "+f"(d[2]), "+f"(d[3])
        : "r"(a[0]), "r"(a[1]), "r"(a[2]), "r"(a[3]), "r"(b[0]), "r"(b[1]));
}
__device__ __forceinline__ uint32_t packbf(float a, float b) {
    __nv_bfloat162 t = __floats2bfloat162_rn(a, b);
    return *reinterpret_cast<uint32_t*>(&t);
}
// hi/lo split of two floats into packed bf16x2 words
__device__ __forceinline__ void split2(float a, float b, uint32_t& hi, uint32_t& lo) {
    float ah = __bfloat162float(__float2bfloat16(a));
    float bh = __bfloat162float(__float2bfloat16(b));
    hi = packbf(ah, bh);
    lo = packbf(a - ah, b - bh);
}

// ======================= mma.sync split-bf16 GEMM ==========================
// C[M,N] (f32) = Ah/Al [M,K] bf16 @ (Bh/Bl [N,K] bf16)^T via 3 MMA products.
#define GBM 128
#define GBN 128
#define GBK 32
#define ROWB 80                      // padded smem row stride (64B data)
#define TILE_B (128 * ROWB)          // 10240 B per tile
#define STG_B  (4 * TILE_B)          // Ah, Al, Bh, Bl
#define NSTAGE 2

__device__ __forceinline__ void g2s_stage(
    uint32_t sbase,
    const __nv_bfloat16* __restrict__ Ah, const __nv_bfloat16* __restrict__ Al,
    const __nv_bfloat16* __restrict__ Bh, const __nv_bfloat16* __restrict__ Bl,
    int m0, int n0, int k0, int K, int tid)
{
#pragma unroll
    for (int i = 0; i < 2; i++) {
        int s = tid + i * 256;               // 0..511
        int r = s >> 2, c = s & 3;           // row 0..127, 16B chunk 0..3
        uint32_t so = (uint32_t)(r * ROWB + c * 16);
        size_t ga = (size_t)(m0 + r) * K + k0 + c * 8;
        size_t gb = (size_t)(n0 + r) * K + k0 + c * 8;
        cpasync16(sbase + 0 * TILE_B + so, Ah + ga);
        cpasync16(sbase + 1 * TILE_B + so, Al + ga);
        cpasync16(sbase + 2 * TILE_B + so, Bh + gb);
        cpasync16(sbase + 3 * TILE_B + so, Bl + gb);
    }
}

__global__ __launch_bounds__(256, 2)
void gemm_mma_kernel(const __nv_bfloat16* __restrict__ Ah,
                     const __nv_bfloat16* __restrict__ Al,
                     const __nv_bfloat16* __restrict__ Bh,
                     const __nv_bfloat16* __restrict__ Bl,
                     float* __restrict__ C, int M, int N, int K)
{
    extern __shared__ char sm_raw[];
    const uint32_t smbase = smem_u32(sm_raw);
    const int tid = threadIdx.x, wid = tid >> 5, lane = tid & 31;
    const int wm = (wid >> 2) * 64;          // warp M offset: 0 / 64
    const int wn = (wid & 3) * 32;           // warp N offset: 0/32/64/96
    const int m0 = blockIdx.y * GBM;
    const int n0 = blockIdx.x * GBN;
    const int lrow = lane & 15;
    const int lch  = (lane >> 4) & 1;        // +1 chunk for k8..15 matrices

    float acc[4][4][4];
#pragma unroll
    for (int a = 0; a < 4; a++)
#pragma unroll
        for (int b = 0; b < 4; b++)
#pragma unroll
            for (int c = 0; c < 4; c++) acc[a][b][c] = 0.0f;

    g2s_stage(smbase + 0 * STG_B, Ah, Al, Bh, Bl, m0, n0, 0, K, tid);
    cpasync_commit();
    g2s_stage(smbase + 1 * STG_B, Ah, Al, Bh, Bl, m0, n0, GBK, K, tid);
    cpasync_commit();

    const int niter = K / GBK;               // 64
    for (int it = 0; it < niter; ++it) {
        cpasync_wait1();
        __syncthreads();

        const uint32_t sb = smbase + (it & 1) * STG_B;

#pragma unroll
        for (int kb = 0; kb < 2; ++kb) {
            const int chunk = kb * 2 + lch;
            uint32_t ah[4][4], al[4][4];
#pragma unroll
            for (int mf = 0; mf < 4; ++mf) {
                uint32_t off = (uint32_t)((wm + mf * 16 + lrow) * ROWB + chunk * 16);
                ldsm_x4(ah[mf][0], ah[mf][1], ah[mf][2], ah[mf][3],
                        sb + 0 * TILE_B + off);
                ldsm_x4(al[mf][0], al[mf][1], al[mf][2], al[mf][3],
                        sb + 1 * TILE_B + off);
            }
            uint32_t bh[4][2], bl[4][2];
#pragma unroll
            for (int np = 0; np < 2; ++np) {
                uint32_t off = (uint32_t)((wn + np * 16 + lrow) * ROWB + chunk * 16);
                uint32_t r0, r1, r2, r3;
                ldsm_x4(r0, r1, r2, r3, sb + 2 * TILE_B + off);
                bh[np*2][0] = r0; bh[np*2][1] = r2;
                bh[np*2+1][0] = r1; bh[np*2+1][1] = r3;
                ldsm_x4(r0, r1, r2, r3, sb + 3 * TILE_B + off);
                bl[np*2][0] = r0; bl[np*2][1] = r2;
                bl[np*2+1][0] = r1; bl[np*2+1][1] = r3;
            }
#pragma unroll
            for (int mf = 0; mf < 4; ++mf)
#pragma unroll
                for (int nf = 0; nf < 4; ++nf) {
                    mma16816(acc[mf][nf], ah[mf], bh[nf]);
                    mma16816(acc[mf][nf], ah[mf], bl[nf]);
                    mma16816(acc[mf][nf], al[mf], bh[nf]);
                }
        }

        __syncthreads();   // stage consumed; safe to refill
        if (it + 2 < niter)
            g2s_stage(smbase + (it & 1) * STG_B, Ah, Al, Bh, Bl,
                      m0, n0, (it + 2) * GBK, K, tid);
        cpasync_commit();
    }

    // epilogue
    const int l4 = lane >> 2, l2 = (lane & 3) * 2;
#pragma unroll
    for (int mf = 0; mf < 4; ++mf) {
        int r0 = m0 + wm + mf * 16 + l4;
#pragma unroll
        for (int nf = 0; nf < 4; ++nf) {
            int cx = n0 + wn + nf * 8 + l2;
            *(float2*)&C[(size_t)r0 * N + cx] =
                make_float2(acc[mf][nf][0], acc[mf][nf][1]);
            *(float2*)&C[(size_t)(r0 + 8) * N + cx] =
                make_float2(acc[mf][nf][2], acc[mf][nf][3]);
        }
    }
}

// ======================= conversion kernels ================================
__global__ __launch_bounds__(256)
void split_kernel(const float* __restrict__ in, __nv_bfloat16* __restrict__ hi,
                  __nv_bfloat16* __restrict__ lo, size_t n)
{
    size_t i = ((size_t)blockIdx.x * blockDim.x + threadIdx.x) * 4;
    if (i >= n) return;
    float4 x = *(const float4*)(in + i);
    __nv_bfloat16 h0 = __float2bfloat16(x.x), h1 = __float2bfloat16(x.y);
    __nv_bfloat16 h2 = __float2bfloat16(x.z), h3 = __float2bfloat16(x.w);
    __nv_bfloat162* hp = (__nv_bfloat162*)(hi + i);
    __nv_bfloat162* lp = (__nv_bfloat162*)(lo + i);
    hp[0] = __nv_bfloat162(h0, h1);
    hp[1] = __nv_bfloat162(h2, h3);
    lp[0] = __nv_bfloat162(__float2bfloat16(x.x - __bfloat162float(h0)),
                           __float2bfloat16(x.y - __bfloat162float(h1)));
    lp[1] = __nv_bfloat162(__float2bfloat16(x.z - __bfloat162float(h2)),
                           __float2bfloat16(x.w - __bfloat162float(h3)));
}

// W [K,N] f32 -> Th/Tl [N,K] bf16
__global__ __launch_bounds__(256)
void transpose_split_kernel(const float* __restrict__ W,
                            __nv_bfloat16* __restrict__ Th,
                            __nv_bfloat16* __restrict__ Tl, int K, int N)
{
    __shared__ float tile[32][33];
    int n0 = blockIdx.x * 32, k0 = blockIdx.y * 32;
    int tx = threadIdx.x, ty = threadIdx.y;   // 32 x 8
#pragma unroll
    for (int i = 0; i < 32; i += 8)
        tile[ty + i][tx] = W[(size_t)(k0 + ty + i) * N + n0 + tx];
    __syncthreads();
#pragma unroll
    for (int i = 0; i < 32; i += 8) {
        float x = tile[tx][ty + i];
        __nv_bfloat16 h = __float2bfloat16(x);
        size_t o = (size_t)(n0 + ty + i) * K + k0 + tx;
        Th[o] = h;
        Tl[o] = __float2bfloat16(x - __bfloat162float(h));
    }
}

// ---------------- RoPE + split to bf16 hi/lo -------------------------------
// qkv: [B*T, 3*C]; writes q/k/v hi+lo: [B,H,T,hd]. Q pre-scaled by 1/sqrt(hd).
__global__ __launch_bounds__(256)
void rope_split_kernel(const float* __restrict__ qkv,
                       __nv_bfloat16* __restrict__ qh, __nv_bfloat16* __restrict__ ql,
                       __nv_bfloat16* __restrict__ kh, __nv_bfloat16* __restrict__ kl,
                       __nv_bfloat16* __restrict__ vh, __nv_bfloat16* __restrict__ vl)
{
    size_t idx = (size_t)blockIdx.x * blockDim.x + threadIdx.x;
    if (idx >= (size_t)BB * TT * CC) return;
    int d = idx & (HD - 1);
    int h = (idx >> 7) & (HH - 1);
    int t = (idx >> 11) & (TT - 1);
    int b = idx >> 20;

    size_t srow = (size_t)(b * TT + t) * N1;
    size_t base = srow + h * HD + d;

    float qv = qkv[base];
    float kv = qkv[base + CC];
    float vv = qkv[base + 2 * CC];

    if (d < ROPE_D) {
        int j = (d < 8) ? d : d - 8;
        float freq = (float)t * powf(10000.0f, -(float)j / 8.0f);
        float c, s;
        sincosf(freq, &s, &c);
        if (d < 8) {
            float qo = qkv[base + 8];
            float ko = qkv[base + CC + 8];
            qv = qv * c - qo * s;
            kv = kv * c - ko * s;
        } else {
            float qo = qkv[base - 8];
            float ko = qkv[base + CC - 8];
            qv = qv * c + qo * s;
            kv = kv * c + ko * s;
        }
    }
    qv *= 0.08838834764831845f;   // fold 1/sqrt(128) into Q

    size_t dst = (((size_t)(b * HH + h)) * TT + t) * HD + d;
    float qhi = __bfloat162float(__float2bfloat16(qv));
    qh[dst] = __float2bfloat16(qv);
    ql[dst] = __float2bfloat16(qv - qhi);
    float khi = __bfloat162float(__float2bfloat16(kv));
    kh[dst] = __float2bfloat16(kv);
    kl[dst] = __float2bfloat16(kv - khi);
    float vhi = __bfloat162float(__float2bfloat16(vv));
    vh[dst] = __float2bfloat16(vv);
    vl[dst] = __float2bfloat16(vv - vhi);
}

// ---------------- Flash attention (mma.sync bf16x3, causal) ----------------
// CTA: 64 q-rows x 64 kv tile, 4 warps (16 q-rows each), hd=128.
#define AQ 64
#define AKV 64
#define ALDB 272                      // bytes per smem row (256B data + 16 pad)
#define ATILE_B (64 * ALDB)           // 17408

__global__ __launch_bounds__(128)
void flash_mma_kernel(const __nv_bfloat16* __restrict__ Qh, const __nv_bfloat16* __restrict__ Ql,
                      const __nv_bfloat16* __restrict__ Kh, const __nv_bfloat16* __restrict__ Kl,
                      const __nv_bfloat16* __restrict__ Vh, const __nv_bfloat16* __restrict__ Vl,
                      __nv_bfloat16* __restrict__ Yh, __nv_bfloat16* __restrict__ Yl)
{
    extern __shared__ char smraw[];
    const uint32_t sb  = smem_u32(smraw);
    const uint32_t sQh = sb,                sQl = sb + ATILE_B;
    const uint32_t sKh = sb + 2*ATILE_B,    sKl = sb + 3*ATILE_B;
    const uint32_t sVh = sb + 4*ATILE_B,    sVl = sb + 5*ATILE_B;

    const int tid = threadIdx.x, lane = tid & 31, wid = tid >> 5;
    const int qt = blockIdx.x, bhid = blockIdx.y;
    const int bb = bhid >> 4, hh = bhid & 15;
    const int q0 = qt * AQ;
    const int l4 = lane >> 2, l2 = lane & 3;
    const int lrow = lane & 15, lch = lane >> 4;
    const int wq = wid * 16;

    // load Q tile (hi/lo) once
    const size_t qg = ((size_t)bhid * TT + q0) * HD;
#pragma unroll
    for (int i = 0; i < 8; i++) {
        int s = tid + i * 128;            // 0..1023
        int r = s >> 4, c = s & 15;       // 64 rows x 16 chunks of 16B
        uint32_t so = (uint32_t)(r * ALDB + c * 16);
        size_t go = qg + (size_t)r * HD + c * 8;
        cpasync16(sQh + so, Qh + go);
        cpasync16(sQl + so, Ql + go);
    }
    cpasync_commit();

    float m0 = -1e30f, m1 = -1e30f, l0 = 0.0f, l1 = 0.0f;
    float oacc[16][4];
#pragma unroll
    for (int i = 0; i < 16; i++)
#pragma unroll
        for (int j = 0; j < 4; j++) oacc[i][j] = 0.0f;

    for (int jt = 0; jt <= qt; ++jt) {
        __syncthreads();                  // K/V smem free (all warps done)
        const size_t kg = ((size_t)bhid * TT + jt * AKV) * HD;
#pragma unroll
        for (int i = 0; i < 8; i++) {
            int s = tid + i * 128;
            int r = s >> 4, c = s & 15;
            uint32_t so = (uint32_t)(r * ALDB + c * 16);
            size_t go = kg + (size_t)r * HD + c * 8;
            cpasync16(sKh + so, Kh + go);
            cpasync16(sKl + so, Kl + go);
            cpasync16(sVh + so, Vh + go);
            cpasync16(sVl + so, Vl + go);
        }
        cpasync_commit();
        cpasync_wait0();
        __syncthreads();

        // ---- S = Q K^T (scaled; fp32 acc; bf16x3) ----
        float sacc[8][4];
#pragma unroll
        for (int i = 0; i < 8; i++)
#pragma unroll
            for (int j = 0; j < 4; j++) sacc[i][j] = 0.0f;

#pragma unroll
        for (int kb = 0; kb < 8; ++kb) {
            const uint32_t co = (uint32_t)((kb * 2 + lch) * 16);
            const uint32_t qa = (uint32_t)((wq + lrow) * ALDB) + co;
            uint32_t ah[4], al[4];
            ldsm_x4(ah[0], ah[1], ah[2], ah[3], sQh + qa);
            ldsm_x4(al[0], al[1], al[2], al[3], sQl + qa);
#pragma unroll
            for (int np = 0; np < 4; ++np) {
                const uint32_t ka = (uint32_t)((np * 16 + lrow) * ALDB) + co;
                uint32_t r0, r1, r2, r3;
                ldsm_x4(r0, r1, r2, r3, sKh + ka);
                uint32_t b0[2] = {r0, r2}, b1[2] = {r1, r3};
                ldsm_x4(r0, r1, r2, r3, sKl + ka);
                uint32_t c0[2] = {r0, r2}, c1[2] = {r1, r3};
                mma16816(sacc[np*2],   ah, b0);
                mma16816(sacc[np*2],   ah, c0);
                mma16816(sacc[np*2],   al, b0);
                mma16816(sacc[np*2+1], ah, b1);
                mma16816(sacc[np*2+1], ah, c1);
                mma16816(sacc[np*2+1], al, b1);
            }
        }

        // ---- causal mask (diagonal tile only) ----
        if (jt == qt) {
            const int r0g = q0 + wq + l4, r1g = r0g + 8;
#pragma unroll
            for (int nf = 0; nf < 8; ++nf) {
                int c0 = jt * AKV + nf * 8 + 2 * l2;
                if (c0     > r0g) sacc[nf][0] = -1e30f;
                if (c0 + 1 > r0g) sacc[nf][1] = -1e30f;
                if (c0     > r1g) sacc[nf][2] = -1e30f;
                if (c0 + 1 > r1g) sacc[nf][3] = -1e30f;
            }
        }

        // ---- online softmax (rows l4 / l4+8; 4 lanes share a row) ----
        float rx0 = -1e30f, rx1 = -1e30f;
#pragma unroll
        for (int nf = 0; nf < 8; ++nf) {
            rx0 = fmaxf(rx0, fmaxf(sacc[nf][0], sacc[nf][1]));
            rx1 = fmaxf(rx1, fmaxf(sacc[nf][2], sacc[nf][3]));
        }
#pragma unroll
        for (int off = 2; off >= 1; off >>= 1) {
            rx0 = fmaxf(rx0, __shfl_xor_sync(0xffffffffu, rx0, off));
            rx1 = fmaxf(rx1, __shfl_xor_sync(0xffffffffu, rx1, off));
        }
        float nm0 = fmaxf(m0, rx0), nm1 = fmaxf(m1, rx1);
        float a0 = __expf(m0 - nm0), a1 = __expf(m1 - nm1);
        m0 = nm0; m1 = nm1;
        float s0 = 0.0f, s1 = 0.0f;
#pragma unroll
        for (int nf = 0; nf < 8; ++nf) {
            sacc[nf][0] = __expf(sacc[nf][0] - nm0); s0 += sacc[nf][0];
            sacc[nf][1] = __expf(sacc[nf][1] - nm0); s0 += sacc[nf][1];
            sacc[nf][2] = __expf(sacc[nf][2] - nm1); s1 += sacc[nf][2];
            sacc[nf][3] = __expf(sacc[nf][3] - nm1); s1 += sacc[nf][3];
        }
#pragma unroll
        for (int off = 2; off >= 1; off >>= 1) {
            s0 += __shfl_xor_sync(0xffffffffu, s0, off);
            s1 += __shfl_xor_sync(0xffffffffu, s1, off);
        }
        l0 = l0 * a0 + s0;
        l1 = l1 * a1 + s1;
#pragma unroll
        for (int nt = 0; nt < 16; ++nt) {
            oacc[nt][0] *= a0; oacc[nt][1] *= a0;
            oacc[nt][2] *= a1; oacc[nt][3] *= a1;
        }

        // ---- O += P V (P hi/lo from registers; V hi/lo via ldmatrix.trans) --
#pragma unroll
        for (int kt = 0; kt < 4; ++kt) {
            uint32_t ph[4], pl[4];
            split2(sacc[2*kt][0],   sacc[2*kt][1],   ph[0], pl[0]);
            split2(sacc[2*kt][2],   sacc[2*kt][3],   ph[1], pl[1]);
            split2(sacc[2*kt+1][0], sacc[2*kt+1][1], ph[2], pl[2]);
            split2(sacc[2*kt+1][2], sacc[2*kt+1][3], ph[3], pl[3]);
#pragma unroll
            for (int nd = 0; nd < 8; ++nd) {
                const uint32_t va =
                    (uint32_t)((kt * 16 + lrow) * ALDB + (nd * 2 + lch) * 16);
                uint32_t h0, h1, h2, h3, x0, x1, x2, x3;
                ldsm_x4_t(h0, h1, h2, h3, sVh + va);
                ldsm_x4_t(x0, x1, x2, x3, sVl + va);
                uint32_t vb0[2] = {h0, h1}, vb1[2] = {h2, h3};
                uint32_t wb0[2] = {x0, x1}, wb1[2] = {x2, x3};
                mma16816(oacc[nd*2],   ph, vb0);
                mma16816(oacc[nd*2],   ph, wb0);
                mma16816(oacc[nd*2],   pl, vb0);
                mma16816(oacc[nd*2+1], ph, vb1);
                mma16816(oacc[nd*2+1], ph, wb1);
                mma16816(oacc[nd*2+1], pl, vb1);
            }
        }
    }

    // ---- epilogue: normalize, hi/lo split, write Yh/Yl [B,T,C] ----
    const float il0 = 1.0f / l0, il1 = 1.0f / l1;
    const int r0g = q0 + wq + l4, r1g = r0g + 8;
#pragma unroll
    for (int nt = 0; nt < 16; ++nt) {
        int col = hh * HD + nt * 8 + 2 * l2;
        size_t o0 = ((size_t)bb * TT + r0g) * CC + col;
        size_t o1 = ((size_t)bb * TT + r1g) * CC + col;
        uint32_t h, l;
        split2(oacc[nt][0] * il0, oacc[nt][1] * il0, h, l);
        *reinterpret_cast<uint32_t*>(Yh + o0) = h;
        *reinterpret_cast<uint32_t*>(Yl + o0) = l;
        split2(oacc[nt][2] * il1, oacc[nt][3] * il1, h, l);
        *reinterpret_cast<uint32_t*>(Yh + o1) = h;
        *reinterpret_cast<uint32_t*>(Yl + o1) = l;
    }
}

// ---------------- launch ----------------------------------------------------
extern "C" void kernel_launch(void* const* d_in, const int* in_sizes, int n_in,
                              void* d_out, int out_size)
{
    const float* x    = (const float*)d_in[0];
    const float* Wqkv = (const float*)d_in[1];
    const float* Wout = (const float*)d_in[2];
    float* out = (float*)d_out;

    float* qkv;
    cudaGetSymbolAddress((void**)&qkv, g_qkv);
    __nv_bfloat16 *xh, *xl, *wqh, *wql, *woh, *wol, *yh, *yl;
    __nv_bfloat16 *qh, *ql, *kh, *kl, *vh, *vl;
    cudaGetSymbolAddress((void**)&xh,  g_xh);
    cudaGetSymbolAddress((void**)&xl,  g_xl);
    cudaGetSymbolAddress((void**)&wqh, g_wqh);
    cudaGetSymbolAddress((void**)&wql, g_wql);
    cudaGetSymbolAddress((void**)&woh, g_woh);
    cudaGetSymbolAddress((void**)&wol, g_wol);
    cudaGetSymbolAddress((void**)&yh,  g_yh);
    cudaGetSymbolAddress((void**)&yl,  g_yl);
    cudaGetSymbolAddress((void**)&qh,  g_q_h);
    cudaGetSymbolAddress((void**)&ql,  g_q_l);
    cudaGetSymbolAddress((void**)&kh,  g_k_h);
    cudaGetSymbolAddress((void**)&kl,  g_k_l);
    cudaGetSymbolAddress((void**)&vh,  g_v_h);
    cudaGetSymbolAddress((void**)&vl,  g_v_l);

    cudaFuncSetAttribute(gemm_mma_kernel,
                         cudaFuncAttributeMaxDynamicSharedMemorySize,
                         NSTAGE * STG_B);
    cudaFuncSetAttribute(flash_mma_kernel,
                         cudaFuncAttributeMaxDynamicSharedMemorySize,
                         6 * ATILE_B);

    // 0a. split x -> bf16 hi/lo
    {
        size_t n = (size_t)M1 * K1;
        split_kernel<<<(unsigned)(n / 4 / 256), 256>>>(x, xh, xl, n);
    }
    // 0b. transpose+split weights
    transpose_split_kernel<<<dim3(N1 / 32, K1 / 32), dim3(32, 8)>>>(Wqkv, wqh, wql, K1, N1);
    transpose_split_kernel<<<dim3(CC / 32, K1 / 32), dim3(32, 8)>>>(Wout, woh, wol, K1, CC);

    // 1. QKV projection (mma.sync bf16x3)
    gemm_mma_kernel<<<dim3(N1 / GBN, M1 / GBM), 256, NSTAGE * STG_B>>>(
        xh, xl, wqh, wql, qkv, M1, N1, K1);

    // 2. RoPE + split to bf16 hi/lo [B,H,T,hd]
    {
        size_t total = (size_t)BB * TT * CC;
        rope_split_kernel<<<(unsigned)((total + 255) / 256), 256>>>(
            qkv, qh, ql, kh, kl, vh, vl);
    }

    // 3. Flash attention on tensor cores (writes yh/yl directly)
    flash_mma_kernel<<<dim3(TT / AQ, BB * HH), 128, 6 * ATILE_B>>>(
        qh, ql, kh, kl, vh, vl, yh, yl);

    // 4. Output projection (mma.sync bf16x3)
    gemm_mma_kernel<<<dim3(CC / GBN, M1 / GBM), 256, NSTAGE * STG_B>>>(
        yh, yl, woh, wol, out, M1, CC, K1);
}

// round 5
// speedup vs baseline: 2.6342x; 1.1553x over previous
#include <cuda_runtime.h>
#include <cuda_bf16.h>
#include <math.h>
#include <stdint.h>

// Problem dims
#define BB 16
#define TT 512
#define CC 2048
#define HH 16
#define HD 128
#define ROPE_D 16
#define M1 (BB*TT)        // 8192
#define N1 (3*CC)         // 6144
#define K1 CC             // 2048

// ---------------- scratch (device globals; no allocation allowed) ----------
__device__ float g_qkv[(size_t)M1 * N1];                 // [8192,6144]

// bf16 hi/lo scratch
__device__ __nv_bfloat16 g_xh[(size_t)M1 * K1];
__device__ __nv_bfloat16 g_xl[(size_t)M1 * K1];
__device__ __nv_bfloat16 g_wqh[(size_t)N1 * K1];         // Wqkv^T [6144,2048]
__device__ __nv_bfloat16 g_wql[(size_t)N1 * K1];
__device__ __nv_bfloat16 g_woh[(size_t)CC * CC];         // Wout^T [2048,2048]
__device__ __nv_bfloat16 g_wol[(size_t)CC * CC];
__device__ __nv_bfloat16 g_yh[(size_t)M1 * CC];
__device__ __nv_bfloat16 g_yl[(size_t)M1 * CC];
// q/k/v hi/lo, [B*H, T, 128]
__device__ __nv_bfloat16 g_q_h[(size_t)BB*HH*TT*HD];
__device__ __nv_bfloat16 g_q_l[(size_t)BB*HH*TT*HD];
__device__ __nv_bfloat16 g_k_h[(size_t)BB*HH*TT*HD];
__device__ __nv_bfloat16 g_k_l[(size_t)BB*HH*TT*HD];
__device__ __nv_bfloat16 g_v_h[(size_t)BB*HH*TT*HD];
__device__ __nv_bfloat16 g_v_l[(size_t)BB*HH*TT*HD];

// ======================= PTX helpers (baseline ISA only) ===================
__device__ __forceinline__ uint32_t smem_u32(const void* p) {
    uint32_t a;
    asm("{ .reg .u64 t; cvta.to.shared.u64 t, %1; cvt.u32.u64 %0, t; }"
        : "=r"(a) : "l"(p));
    return a;
}
__device__ __forceinline__ void cpasync16(uint32_t dst, const void* src) {
    asm volatile("cp.async.cg.shared.global [%0], [%1], 16;"
                 :: "r"(dst), "l"(src) : "memory");
}
__device__ __forceinline__ void cpasync_commit() {
    asm volatile("cp.async.commit_group;" ::: "memory");
}
__device__ __forceinline__ void cpasync_wait1() {
    asm volatile("cp.async.wait_group 1;" ::: "memory");
}
__device__ __forceinline__ void cpasync_wait0() {
    asm volatile("cp.async.wait_group 0;" ::: "memory");
}
__device__ __forceinline__ void ldsm_x4(uint32_t& r0, uint32_t& r1,
                                        uint32_t& r2, uint32_t& r3, uint32_t a) {
    asm volatile("ldmatrix.sync.aligned.m8n8.x4.shared.b16 {%0,%1,%2,%3}, [%4];"
                 : "=r"(r0), "=r"(r1), "=r"(r2), "=r"(r3) : "r"(a));
}
__device__ __forceinline__ void ldsm_x4_t(uint32_t& r0, uint32_t& r1,
                                          uint32_t& r2, uint32_t& r3, uint32_t a) {
    asm volatile("ldmatrix.sync.aligned.m8n8.x4.trans.shared.b16 {%0,%1,%2,%3}, [%4];"
                 : "=r"(r0), "=r"(r1), "=r"(r2), "=r"(r3) : "r"(a));
}
__device__ __forceinline__ void mma16816(float* d, const uint32_t* a,
                                         const uint32_t* b) {
    asm volatile(
        "mma.sync.aligned.m16n8k16.row.col.f32.bf16.bf16.f32 "
        "{%0,%1,%2,%3}, {%4,%5,%6,%7}, {%8,%9}, {%0,%1,%2,%3};"
        : "+f"(d[0]), "+f"(d[1]), "+f"(d[2]), "+f"(d[3])
        : "r"(a[0]), "r"(a[1]), "r"(a[2]), "r"(a[3]), "r"(b[0]), "r"(b[1]));
}
__device__ __forceinline__ uint32_t packbf(float a, float b) {
    __nv_bfloat162 t = __floats2bfloat162_rn(a, b);
    return *reinterpret_cast<uint32_t*>(&t);
}
// hi/lo split of two floats into packed bf16x2 words
__device__ __forceinline__ void split2(float a, float b, uint32_t& hi, uint32_t& lo) {
    float ah = __bfloat162float(__float2bfloat16(a));
    float bh = __bfloat162float(__float2bfloat16(b));
    hi = packbf(ah, bh);
    lo = packbf(a - ah, b - bh);
}

// ======================= mma.sync split-bf16 GEMM ==========================
// C[M,N] (f32) = Ah/Al [M,K] bf16 @ (Bh/Bl [N,K] bf16)^T via 3 MMA products.
// Tiles: 128 rows x 64B (K=32 bf16), XOR-swizzled 16B chunks, no padding.
#define GBM 128
#define GBN 128
#define GBK 32
#define TILE_B (128 * 64)            // 8192 B per tile
#define STG_B  (4 * TILE_B)          // Ah, Al, Bh, Bl = 32768
#define NSTAGE 3

// conflict-free smem offset: row stride 64B, chunk (16B) XOR'd with (row>>1)&3
__device__ __forceinline__ uint32_t swz(int row, int chunk) {
    return (uint32_t)((row << 6) + ((chunk ^ ((row >> 1) & 3)) << 4));
}

__device__ __forceinline__ void g2s_stage(
    uint32_t sbase,
    const __nv_bfloat16* __restrict__ Ah, const __nv_bfloat16* __restrict__ Al,
    const __nv_bfloat16* __restrict__ Bh, const __nv_bfloat16* __restrict__ Bl,
    int m0, int n0, int k0, int K, int tid)
{
#pragma unroll
    for (int i = 0; i < 2; i++) {
        int s = tid + i * 256;               // 0..511
        int r = s >> 2, c = s & 3;           // row 0..127, 16B chunk 0..3
        uint32_t so = swz(r, c);
        size_t ga = (size_t)(m0 + r) * K + k0 + c * 8;
        size_t gb = (size_t)(n0 + r) * K + k0 + c * 8;
        cpasync16(sbase + 0 * TILE_B + so, Ah + ga);
        cpasync16(sbase + 1 * TILE_B + so, Al + ga);
        cpasync16(sbase + 2 * TILE_B + so, Bh + gb);
        cpasync16(sbase + 3 * TILE_B + so, Bl + gb);
    }
}

__global__ __launch_bounds__(256, 2)
void gemm_mma_kernel(const __nv_bfloat16* __restrict__ Ah,
                     const __nv_bfloat16* __restrict__ Al,
                     const __nv_bfloat16* __restrict__ Bh,
                     const __nv_bfloat16* __restrict__ Bl,
                     float* __restrict__ C, int M, int N, int K)
{
    extern __shared__ char sm_raw[];
    const uint32_t smbase = smem_u32(sm_raw);
    const int tid = threadIdx.x, wid = tid >> 5, lane = tid & 31;
    const int wm = (wid >> 2) * 64;          // warp M offset: 0 / 64
    const int wn = (wid & 3) * 32;           // warp N offset: 0/32/64/96
    const int m0 = blockIdx.y * GBM;
    const int n0 = blockIdx.x * GBN;
    const int lrow = lane & 15;
    const int lch  = (lane >> 4) & 1;        // +1 chunk for k8..15 matrices

    float acc[4][4][4];
#pragma unroll
    for (int a = 0; a < 4; a++)
#pragma unroll
        for (int b = 0; b < 4; b++)
#pragma unroll
            for (int c = 0; c < 4; c++) acc[a][b][c] = 0.0f;

    g2s_stage(smbase + 0 * STG_B, Ah, Al, Bh, Bl, m0, n0, 0, K, tid);
    cpasync_commit();
    g2s_stage(smbase + 1 * STG_B, Ah, Al, Bh, Bl, m0, n0, GBK, K, tid);
    cpasync_commit();

    const int niter = K / GBK;               // 64
    int stage = 0, nstage = 2;
    for (int it = 0; it < niter; ++it) {
        cpasync_wait1();
        __syncthreads();

        // refill the just-freed stage BEFORE compute (intra-CTA overlap)
        if (it + 2 < niter)
            g2s_stage(smbase + nstage * STG_B, Ah, Al, Bh, Bl,
                      m0, n0, (it + 2) * GBK, K, tid);
        cpasync_commit();
        if (++nstage == NSTAGE) nstage = 0;

        const uint32_t sb = smbase + stage * STG_B;
        if (++stage == NSTAGE) stage = 0;

#pragma unroll
        for (int kb = 0; kb < 2; ++kb) {
            const int chunk = kb * 2 + lch;
            uint32_t ah[4][4], al[4][4];
#pragma unroll
            for (int mf = 0; mf < 4; ++mf) {
                uint32_t off = swz(wm + mf * 16 + lrow, chunk);
                ldsm_x4(ah[mf][0], ah[mf][1], ah[mf][2], ah[mf][3],
                        sb + 0 * TILE_B + off);
                ldsm_x4(al[mf][0], al[mf][1], al[mf][2], al[mf][3],
                        sb + 1 * TILE_B + off);
            }
            uint32_t bh[4][2], bl[4][2];
#pragma unroll
            for (int np = 0; np < 2; ++np) {
                uint32_t off = swz(wn + np * 16 + lrow, chunk);
                uint32_t r0, r1, r2, r3;
                ldsm_x4(r0, r1, r2, r3, sb + 2 * TILE_B + off);
                bh[np*2][0] = r0; bh[np*2][1] = r2;
                bh[np*2+1][0] = r1; bh[np*2+1][1] = r3;
                ldsm_x4(r0, r1, r2, r3, sb + 3 * TILE_B + off);
                bl[np*2][0] = r0; bl[np*2][1] = r2;
                bl[np*2+1][0] = r1; bl[np*2+1][1] = r3;
            }
#pragma unroll
            for (int mf = 0; mf < 4; ++mf)
#pragma unroll
                for (int nf = 0; nf < 4; ++nf) {
                    mma16816(acc[mf][nf], ah[mf], bh[nf]);
                    mma16816(acc[mf][nf], ah[mf], bl[nf]);
                    mma16816(acc[mf][nf], al[mf], bh[nf]);
                }
        }
    }

    // epilogue
    const int l4 = lane >> 2, l2 = (lane & 3) * 2;
#pragma unroll
    for (int mf = 0; mf < 4; ++mf) {
        int r0 = m0 + wm + mf * 16 + l4;
#pragma unroll
        for (int nf = 0; nf < 4; ++nf) {
            int cx = n0 + wn + nf * 8 + l2;
            *(float2*)&C[(size_t)r0 * N + cx] =
                make_float2(acc[mf][nf][0], acc[mf][nf][1]);
            *(float2*)&C[(size_t)(r0 + 8) * N + cx] =
                make_float2(acc[mf][nf][2], acc[mf][nf][3]);
        }
    }
}

// ======================= conversion kernels ================================
__global__ __launch_bounds__(256)
void split_kernel(const float* __restrict__ in, __nv_bfloat16* __restrict__ hi,
                  __nv_bfloat16* __restrict__ lo, size_t n)
{
    size_t i = ((size_t)blockIdx.x * blockDim.x + threadIdx.x) * 4;
    if (i >= n) return;
    float4 x = *(const float4*)(in + i);
    __nv_bfloat16 h0 = __float2bfloat16(x.x), h1 = __float2bfloat16(x.y);
    __nv_bfloat16 h2 = __float2bfloat16(x.z), h3 = __float2bfloat16(x.w);
    __nv_bfloat162* hp = (__nv_bfloat162*)(hi + i);
    __nv_bfloat162* lp = (__nv_bfloat162*)(lo + i);
    hp[0] = __nv_bfloat162(h0, h1);
    hp[1] = __nv_bfloat162(h2, h3);
    lp[0] = __nv_bfloat162(__float2bfloat16(x.x - __bfloat162float(h0)),
                           __float2bfloat16(x.y - __bfloat162float(h1)));
    lp[1] = __nv_bfloat162(__float2bfloat16(x.z - __bfloat162float(h2)),
                           __float2bfloat16(x.w - __bfloat162float(h3)));
}

// W [K,N] f32 -> Th/Tl [N,K] bf16
__global__ __launch_bounds__(256)
void transpose_split_kernel(const float* __restrict__ W,
                            __nv_bfloat16* __restrict__ Th,
                            __nv_bfloat16* __restrict__ Tl, int K, int N)
{
    __shared__ float tile[32][33];
    int n0 = blockIdx.x * 32, k0 = blockIdx.y * 32;
    int tx = threadIdx.x, ty = threadIdx.y;   // 32 x 8
#pragma unroll
    for (int i = 0; i < 32; i += 8)
        tile[ty + i][tx] = W[(size_t)(k0 + ty + i) * N + n0 + tx];
    __syncthreads();
#pragma unroll
    for (int i = 0; i < 32; i += 8) {
        float x = tile[tx][ty + i];
        __nv_bfloat16 h = __float2bfloat16(x);
        size_t o = (size_t)(n0 + ty + i) * K + k0 + tx;
        Th[o] = h;
        Tl[o] = __float2bfloat16(x - __bfloat162float(h));
    }
}

// ---------------- RoPE + split to bf16 hi/lo -------------------------------
__global__ __launch_bounds__(256)
void rope_split_kernel(const float* __restrict__ qkv,
                       __nv_bfloat16* __restrict__ qh, __nv_bfloat16* __restrict__ ql,
                       __nv_bfloat16* __restrict__ kh, __nv_bfloat16* __restrict__ kl,
                       __nv_bfloat16* __restrict__ vh, __nv_bfloat16* __restrict__ vl)
{
    size_t idx = (size_t)blockIdx.x * blockDim.x + threadIdx.x;
    if (idx >= (size_t)BB * TT * CC) return;
    int d = idx & (HD - 1);
    int h = (idx >> 7) & (HH - 1);
    int t = (idx >> 11) & (TT - 1);
    int b = idx >> 20;

    size_t srow = (size_t)(b * TT + t) * N1;
    size_t base = srow + h * HD + d;

    float qv = qkv[base];
    float kv = qkv[base + CC];
    float vv = qkv[base + 2 * CC];

    if (d < ROPE_D) {
        int j = (d < 8) ? d : d - 8;
        float freq = (float)t * powf(10000.0f, -(float)j / 8.0f);
        float c, s;
        sincosf(freq, &s, &c);
        if (d < 8) {
            float qo = qkv[base + 8];
            float ko = qkv[base + CC + 8];
            qv = qv * c - qo * s;
            kv = kv * c - ko * s;
        } else {
            float qo = qkv[base - 8];
            float ko = qkv[base + CC - 8];
            qv = qv * c + qo * s;
            kv = kv * c + ko * s;
        }
    }
    qv *= 0.08838834764831845f;   // fold 1/sqrt(128) into Q

    size_t dst = (((size_t)(b * HH + h)) * TT + t) * HD + d;
    float qhi = __bfloat162float(__float2bfloat16(qv));
    qh[dst] = __float2bfloat16(qv);
    ql[dst] = __float2bfloat16(qv - qhi);
    float khi = __bfloat162float(__float2bfloat16(kv));
    kh[dst] = __float2bfloat16(kv);
    kl[dst] = __float2bfloat16(kv - khi);
    float vhi = __bfloat162float(__float2bfloat16(vv));
    vh[dst] = __float2bfloat16(vv);
    vl[dst] = __float2bfloat16(vv - vhi);
}

// ---------------- Flash attention (mma.sync bf16x3, causal) ----------------
// CTA: 64 q-rows x 64 kv tile, 4 warps (16 q-rows each), hd=128.
#define AQ 64
#define AKV 64
#define ALDB 272                      // bytes per smem row (256B data + 16 pad)
#define ATILE_B (64 * ALDB)           // 17408

__global__ __launch_bounds__(128, 2)
void flash_mma_kernel(const __nv_bfloat16* __restrict__ Qh, const __nv_bfloat16* __restrict__ Ql,
                      const __nv_bfloat16* __restrict__ Kh, const __nv_bfloat16* __restrict__ Kl,
                      const __nv_bfloat16* __restrict__ Vh, const __nv_bfloat16* __restrict__ Vl,
                      __nv_bfloat16* __restrict__ Yh, __nv_bfloat16* __restrict__ Yl)
{
    extern __shared__ char smraw[];
    const uint32_t sb  = smem_u32(smraw);
    const uint32_t sQh = sb,                sQl = sb + ATILE_B;
    const uint32_t sKh = sb + 2*ATILE_B,    sKl = sb + 3*ATILE_B;
    const uint32_t sVh = sb + 4*ATILE_B,    sVl = sb + 5*ATILE_B;

    const int tid = threadIdx.x, lane = tid & 31, wid = tid >> 5;
    const int qt = blockIdx.x, bhid = blockIdx.y;
    const int bb = bhid >> 4, hh = bhid & 15;
    const int q0 = qt * AQ;
    const int l4 = lane >> 2, l2 = lane & 3;
    const int lrow = lane & 15, lch = lane >> 4;
    const int wq = wid * 16;

    // load Q tile (hi/lo) once
    const size_t qg = ((size_t)bhid * TT + q0) * HD;
#pragma unroll
    for (int i = 0; i < 8; i++) {
        int s = tid + i * 128;            // 0..1023
        int r = s >> 4, c = s & 15;       // 64 rows x 16 chunks of 16B
        uint32_t so = (uint32_t)(r * ALDB + c * 16);
        size_t go = qg + (size_t)r * HD + c * 8;
        cpasync16(sQh + so, Qh + go);
        cpasync16(sQl + so, Ql + go);
    }
    cpasync_commit();

    float m0 = -1e30f, m1 = -1e30f, l0 = 0.0f, l1 = 0.0f;
    float oacc[16][4];
#pragma unroll
    for (int i = 0; i < 16; i++)
#pragma unroll
        for (int j = 0; j < 4; j++) oacc[i][j] = 0.0f;

    for (int jt = 0; jt <= qt; ++jt) {
        __syncthreads();                  // K/V smem free (all warps done)
        const size_t kg = ((size_t)bhid * TT + jt * AKV) * HD;
#pragma unroll
        for (int i = 0; i < 8; i++) {
            int s = tid + i * 128;
            int r = s >> 4, c = s & 15;
            uint32_t so = (uint32_t)(r * ALDB + c * 16);
            size_t go = kg + (size_t)r * HD + c * 8;
            cpasync16(sKh + so, Kh + go);
            cpasync16(sKl + so, Kl + go);
            cpasync16(sVh + so, Vh + go);
            cpasync16(sVl + so, Vl + go);
        }
        cpasync_commit();
        cpasync_wait0();
        __syncthreads();

        // ---- S = Q K^T (scaled; fp32 acc; bf16x3) ----
        float sacc[8][4];
#pragma unroll
        for (int i = 0; i < 8; i++)
#pragma unroll
            for (int j = 0; j < 4; j++) sacc[i][j] = 0.0f;

#pragma unroll
        for (int kb = 0; kb < 8; ++kb) {
            const uint32_t co = (uint32_t)((kb * 2 + lch) * 16);
            const uint32_t qa = (uint32_t)((wq + lrow) * ALDB) + co;
            uint32_t ah[4], al[4];
            ldsm_x4(ah[0], ah[1], ah[2], ah[3], sQh + qa);
            ldsm_x4(al[0], al[1], al[2], al[3], sQl + qa);
#pragma unroll
            for (int np = 0; np < 4; ++np) {
                const uint32_t ka = (uint32_t)((np * 16 + lrow) * ALDB) + co;
                uint32_t r0, r1, r2, r3;
                ldsm_x4(r0, r1, r2, r3, sKh + ka);
                uint32_t b0[2] = {r0, r2}, b1[2] = {r1, r3};
                ldsm_x4(r0, r1, r2, r3, sKl + ka);
                uint32_t c0[2] = {r0, r2}, c1[2] = {r1, r3};
                mma16816(sacc[np*2],   ah, b0);
                mma16816(sacc[np*2],   ah, c0);
                mma16816(sacc[np*2],   al, b0);
                mma16816(sacc[np*2+1], ah, b1);
                mma16816(sacc[np*2+1], ah, c1);
                mma16816(sacc[np*2+1], al, b1);
            }
        }

        // ---- causal mask (diagonal tile only) ----
        if (jt == qt) {
            const int r0g = q0 + wq + l4, r1g = r0g + 8;
#pragma unroll
            for (int nf = 0; nf < 8; ++nf) {
                int c0 = jt * AKV + nf * 8 + 2 * l2;
                if (c0     > r0g) sacc[nf][0] = -1e30f;
                if (c0 + 1 > r0g) sacc[nf][1] = -1e30f;
                if (c0     > r1g) sacc[nf][2] = -1e30f;
                if (c0 + 1 > r1g) sacc[nf][3] = -1e30f;
            }
        }

        // ---- online softmax (rows l4 / l4+8; 4 lanes share a row) ----
        float rx0 = -1e30f, rx1 = -1e30f;
#pragma unroll
        for (int nf = 0; nf < 8; ++nf) {
            rx0 = fmaxf(rx0, fmaxf(sacc[nf][0], sacc[nf][1]));
            rx1 = fmaxf(rx1, fmaxf(sacc[nf][2], sacc[nf][3]));
        }
#pragma unroll
        for (int off = 2; off >= 1; off >>= 1) {
            rx0 = fmaxf(rx0, __shfl_xor_sync(0xffffffffu, rx0, off));
            rx1 = fmaxf(rx1, __shfl_xor_sync(0xffffffffu, rx1, off));
        }
        float nm0 = fmaxf(m0, rx0), nm1 = fmaxf(m1, rx1);
        float a0 = __expf(m0 - nm0), a1 = __expf(m1 - nm1);
        m0 = nm0; m1 = nm1;
        float s0 = 0.0f, s1 = 0.0f;
#pragma unroll
        for (int nf = 0; nf < 8; ++nf) {
            sacc[nf][0] = __expf(sacc[nf][0] - nm0); s0 += sacc[nf][0];
            sacc[nf][1] = __expf(sacc[nf][1] - nm0); s0 += sacc[nf][1];
            sacc[nf][2] = __expf(sacc[nf][2] - nm1); s1 += sacc[nf][2];
            sacc[nf][3] = __expf(sacc[nf][3] - nm1); s1 += sacc[nf][3];
        }
#pragma unroll
        for (int off = 2; off >= 1; off >>= 1) {
            s0 += __shfl_xor_sync(0xffffffffu, s0, off);
            s1 += __shfl_xor_sync(0xffffffffu, s1, off);
        }
        l0 = l0 * a0 + s0;
        l1 = l1 * a1 + s1;
#pragma unroll
        for (int nt = 0; nt < 16; ++nt) {
            oacc[nt][0] *= a0; oacc[nt][1] *= a0;
            oacc[nt][2] *= a1; oacc[nt][3] *= a1;
        }

        // ---- O += P V (P hi/lo from registers; V hi/lo via ldmatrix.trans) --
#pragma unroll
        for (int kt = 0; kt < 4; ++kt) {
            uint32_t ph[4], pl[4];
            split2(sacc[2*kt][0],   sacc[2*kt][1],   ph[0], pl[0]);
            split2(sacc[2*kt][2],   sacc[2*kt][3],   ph[1], pl[1]);
            split2(sacc[2*kt+1][0], sacc[2*kt+1][1], ph[2], pl[2]);
            split2(sacc[2*kt+1][2], sacc[2*kt+1][3], ph[3], pl[3]);
#pragma unroll
            for (int nd = 0; nd < 8; ++nd) {
                const uint32_t va =
                    (uint32_t)((kt * 16 + lrow) * ALDB + (nd * 2 + lch) * 16);
                uint32_t h0, h1, h2, h3, x0, x1, x2, x3;
                ldsm_x4_t(h0, h1, h2, h3, sVh + va);
                ldsm_x4_t(x0, x1, x2, x3, sVl + va);
                uint32_t vb0[2] = {h0, h1}, vb1[2] = {h2, h3};
                uint32_t wb0[2] = {x0, x1}, wb1[2] = {x2, x3};
                mma16816(oacc[nd*2],   ph, vb0);
                mma16816(oacc[nd*2],   ph, wb0);
                mma16816(oacc[nd*2],   pl, vb0);
                mma16816(oacc[nd*2+1], ph, vb1);
                mma16816(oacc[nd*2+1], ph, wb1);
                mma16816(oacc[nd*2+1], pl, vb1);
            }
        }
    }

    // ---- epilogue: normalize, hi/lo split, write Yh/Yl [B,T,C] ----
    const float il0 = 1.0f / l0, il1 = 1.0f / l1;
    const int r0g = q0 + wq + l4, r1g = r0g + 8;
#pragma unroll
    for (int nt = 0; nt < 16; ++nt) {
        int col = hh * HD + nt * 8 + 2 * l2;
        size_t o0 = ((size_t)bb * TT + r0g) * CC + col;
        size_t o1 = ((size_t)bb * TT + r1g) * CC + col;
        uint32_t h, l;
        split2(oacc[nt][0] * il0, oacc[nt][1] * il0, h, l);
        *reinterpret_cast<uint32_t*>(Yh + o0) = h;
        *reinterpret_cast<uint32_t*>(Yl + o0) = l;
        split2(oacc[nt][2] * il1, oacc[nt][3] * il1, h, l);
        *reinterpret_cast<uint32_t*>(Yh + o1) = h;
        *reinterpret_cast<uint32_t*>(Yl + o1) = l;
    }
}

// ---------------- launch ----------------------------------------------------
extern "C" void kernel_launch(void* const* d_in, const int* in_sizes, int n_in,
                              void* d_out, int out_size)
{
    const float* x    = (const float*)d_in[0];
    const float* Wqkv = (const float*)d_in[1];
    const float* Wout = (const float*)d_in[2];
    float* out = (float*)d_out;

    float* qkv;
    cudaGetSymbolAddress((void**)&qkv, g_qkv);
    __nv_bfloat16 *xh, *xl, *wqh, *wql, *woh, *wol, *yh, *yl;
    __nv_bfloat16 *qh, *ql, *kh, *kl, *vh, *vl;
    cudaGetSymbolAddress((void**)&xh,  g_xh);
    cudaGetSymbolAddress((void**)&xl,  g_xl);
    cudaGetSymbolAddress((void**)&wqh, g_wqh);
    cudaGetSymbolAddress((void**)&wql, g_wql);
    cudaGetSymbolAddress((void**)&woh, g_woh);
    cudaGetSymbolAddress((void**)&wol, g_wol);
    cudaGetSymbolAddress((void**)&yh,  g_yh);
    cudaGetSymbolAddress((void**)&yl,  g_yl);
    cudaGetSymbolAddress((void**)&qh,  g_q_h);
    cudaGetSymbolAddress((void**)&ql,  g_q_l);
    cudaGetSymbolAddress((void**)&kh,  g_k_h);
    cudaGetSymbolAddress((void**)&kl,  g_k_l);
    cudaGetSymbolAddress((void**)&vh,  g_v_h);
    cudaGetSymbolAddress((void**)&vl,  g_v_l);

    cudaFuncSetAttribute(gemm_mma_kernel,
                         cudaFuncAttributeMaxDynamicSharedMemorySize,
                         NSTAGE * STG_B);
    cudaFuncSetAttribute(flash_mma_kernel,
                         cudaFuncAttributeMaxDynamicSharedMemorySize,
                         6 * ATILE_B);

    // 0a. split x -> bf16 hi/lo
    {
        size_t n = (size_t)M1 * K1;
        split_kernel<<<(unsigned)(n / 4 / 256), 256>>>(x, xh, xl, n);
    }
    // 0b. transpose+split weights
    transpose_split_kernel<<<dim3(N1 / 32, K1 / 32), dim3(32, 8)>>>(Wqkv, wqh, wql, K1, N1);
    transpose_split_kernel<<<dim3(CC / 32, K1 / 32), dim3(32, 8)>>>(Wout, woh, wol, K1, CC);

    // 1. QKV projection (mma.sync bf16x3)
    gemm_mma_kernel<<<dim3(N1 / GBN, M1 / GBM), 256, NSTAGE * STG_B>>>(
        xh, xl, wqh, wql, qkv, M1, N1, K1);

    // 2. RoPE + split to bf16 hi/lo [B,H,T,hd]
    {
        size_t total = (size_t)BB * TT * CC;
        rope_split_kernel<<<(unsigned)((total + 255) / 256), 256>>>(
            qkv, qh, ql, kh, kl, vh, vl);
    }

    // 3. Flash attention on tensor cores (writes yh/yl directly)
    flash_mma_kernel<<<dim3(TT / AQ, BB * HH), 128, 6 * ATILE_B>>>(
        qh, ql, kh, kl, vh, vl, yh, yl);

    // 4. Output projection (mma.sync bf16x3)
    gemm_mma_kernel<<<dim3(CC / GBN, M1 / GBM), 256, NSTAGE * STG_B>>>(
        yh, yl, woh, wol, out, M1, CC, K1);
}